// round 15
// baseline (speedup 1.0000x reference)
#include <cuda_runtime.h>
#include <cuda_bf16.h>

// DETR3D feature sampling. B=1, NC=6 cams, C=256, nq=900, 4 FPN levels
// (H,W): (116,200) (58,100) (29,50) (15,25).
// Output: ref3d[900,3] | sampled[256,900,6,1,4] | mask[900,6].
//
// R14: SPLIT fill + gather. ~87% of (query,cam) samples are out-of-frustum;
// previous single-kernel versions burned most of their instruction stream and
// store wavefronts on loops whose only effect was writing zeros.
//   Kernel 1 (fs_fill): zero the entire sampled region with perfectly
//     coalesced float4 stores (exactly 5400 blocks x 256 threads x 16B),
//     plus the ref3d passthrough.
//   Kernel 2 (fs_gather): 2700 blocks x 8 warps; 4 warps per sample, each
//     warp owns 64 channels. Warp recomputes the (cheap) projection, writes
//     mask (one designated warp per sample), and EXITS if the sample is
//     invalid. Valid warps gather with the proven corner-pair coalescing:
//       lane = c8*4 + lp*2 + xside
//     xside lanes pair-coalesce the two x columns (one L1 wavefront per
//     row-load), lp lanes carry level pairs {0,1}/{2,3}, and after
//     shfl-reductions one lane per channel stores a float4 covering all 4
//     levels (output minor dim is level, 16B aligned).
// Invalid corners: indices clamped, weights zeroed (exact — reference
// multiplies by valid=0). Levels with no valid corner keep j=0/w=0 and the
// harmless p[0] loads contribute 0.

#define FS_EPS 1e-5f
#define NQ 900
#define NCAM 6
#define NCH 256
#define NSAMP (NQ * NCAM)            // 5400
#define SAMPLED_FLOATS (NCH * NQ * NCAM * 4)  // 5529600

// ---------------- Kernel 1: zero-fill sampled + ref3d copy ----------------
__global__ __launch_bounds__(256)
void fs_fill(const float* __restrict__ ref, float* __restrict__ out)
{
    const unsigned i = blockIdx.x * 256u + threadIdx.x;   // 0 .. 1382399
    // sampled starts at out+2700 floats = 10800 bytes (16B aligned)
    float4* dst = reinterpret_cast<float4*>(out + NQ * 3);
    dst[i] = make_float4(0.f, 0.f, 0.f, 0.f);             // exact cover: 5400*256 float4
    if (i < NQ * 3) out[i] = ref[i];                      // ref3d passthrough
}

// ---------------- Kernel 2: gather valid samples ----------------
__global__ __launch_bounds__(256)
void fs_gather(
    const float* __restrict__ f0,   // [6,256,116,200]
    const float* __restrict__ f1,   // [6,256, 58,100]
    const float* __restrict__ f2,   // [6,256, 29, 50]
    const float* __restrict__ f3,   // [6,256, 15, 25]
    const float* __restrict__ ref,  // [900,3]
    const float* __restrict__ pc,   // [6]
    const float* __restrict__ img,  // [2] = {H=928, W=1600}
    const float* __restrict__ l2i,  // [6,4,4]
    float* __restrict__ out)
{
    const int t    = threadIdx.x;
    const int w    = t >> 5;             // warp 0..7
    const int lane = t & 31;
    const int samp = blockIdx.x * 2 + (w >> 2);   // 0..5399
    const int chbase = (w & 3) * 64;              // this warp's channel window
    const int q = samp / NCAM;
    const int n = samp - q * NCAM;

    float* sampled = out + NQ * 3;
    float* maskout = out + NQ * 3 + SAMPLED_FLOATS;

    // --- projection (all lanes redundantly; matches reference arithmetic) ---
    const float rx = ref[q * 3 + 0];
    const float ry = ref[q * 3 + 1];
    const float rz = ref[q * 3 + 2];
    const float px = rx * (pc[3] - pc[0]) + pc[0];
    const float py = ry * (pc[4] - pc[1]) + pc[1];
    const float pz = rz * (pc[5] - pc[2]) + pc[2];
    const float* M = l2i + n * 16;
    const float c0 = M[0] * px + M[1] * py + M[2]  * pz + M[3];
    const float c1 = M[4] * px + M[5] * py + M[6]  * pz + M[7];
    const float c2 = M[8] * px + M[9] * py + M[10] * pz + M[11];
    const float zd = fmaxf(c2, FS_EPS);
    const float gx = (c0 / zd / img[1] - 0.5f) * 2.0f;
    const float gy = (c1 / zd / img[0] - 0.5f) * 2.0f;

    // mask: one warp per sample writes it (before any early exit)
    if ((w & 3) == 0 && lane == 0) {
        const bool m = (c2 > FS_EPS) &&
                       (gx > -1.0f) && (gx < 1.0f) &&
                       (gy > -1.0f) && (gy < 1.0f);
        maskout[samp] = m ? 1.0f : 0.0f;
    }

    // --- lane decomposition ---
    const int xside = lane & 1;          // x column of the bilinear pair
    const int lp    = (lane >> 1) & 1;   // level pair: {0,1} or {2,3}
    const int c8    = lane >> 2;         // channel slot 0..7

    const int   WA  = lp ? 50 : 200;
    const int   HA  = lp ? 29 : 116;
    const int   WB  = lp ? 25 : 100;
    const int   HB  = lp ? 15 : 58;
    const int   HWA = WA * HA;
    const int   HWB = WB * HB;
    const float* fA = lp ? f2 : f0;
    const float* fB = lp ? f3 : f1;

    int   jA0 = 0, jA1 = 0, jB0 = 0, jB1 = 0;
    float wA0 = 0.f, wA1 = 0.f, wB0 = 0.f, wB1 = 0.f;
    bool  anyAB = false;

    #pragma unroll
    for (int half = 0; half < 2; half++) {
        const int Wl = half ? WB : WA;
        const int Hl = half ? HB : HA;

        const float ix  = ((gx + 1.0f) * (float)Wl - 1.0f) * 0.5f;
        const float iy  = ((gy + 1.0f) * (float)Hl - 1.0f) * 0.5f;
        const float ix0 = floorf(ix);
        const float iy0 = floorf(iy);
        const float wx1 = ix - ix0;
        const float wy1 = iy - iy0;
        const float wx0 = 1.0f - wx1;
        const float wy0 = 1.0f - wy1;

        // side validity (NaN comparisons false -> invalid)
        const bool vx0 = (ix0        >= 0.0f) && (ix0        <= (float)(Wl - 1));
        const bool vx1 = (ix0 + 1.0f >= 0.0f) && (ix0 + 1.0f <= (float)(Wl - 1));
        const bool vy0 = (iy0        >= 0.0f) && (iy0        <= (float)(Hl - 1));
        const bool vy1 = (iy0 + 1.0f >= 0.0f) && (iy0 + 1.0f <= (float)(Hl - 1));
        const bool anyvalid = (vx0 | vx1) & (vy0 | vy1);

        if (anyvalid) {
            anyAB = true;
            // anyvalid implies ix0 in [-1,Wl-1], iy0 in [-1,Hl-1] -> safe int conv
            const int ixi = (int)ix0;
            const int iyi = (int)iy0;
            const int xc0 = max(ixi,     0);
            const int xc1 = min(ixi + 1, Wl - 1);
            const int yr0 = max(iyi,     0) * Wl;
            const int yr1 = min(iyi + 1, Hl - 1) * Wl;

            const int   xs  = xside ? xc1 : xc0;   // this lane's column (clamped)
            const bool  vxs = xside ? vx1 : vx0;
            const float wxs = xside ? wx1 : wx0;
            const int   k0  = yr0 + xs;
            const int   k1  = yr1 + xs;
            const float u0  = (vy0 && vxs) ? wy0 * wxs : 0.f;  // zero invalid corners
            const float u1  = (vy1 && vxs) ? wy1 * wxs : 0.f;
            if (half == 0) { jA0 = k0; jA1 = k1; wA0 = u0; wA1 = u1; }
            else           { jB0 = k0; jB1 = k1; wB0 = u0; wB1 = u1; }
        }
    }

    // warp-uniform early exit: no level of this sample touches the image
    if (__ballot_sync(0xffffffffu, anyAB) == 0u) return;

    // --- channel loop: 8 iterations x 8 channels ---
    // feat element: f[(n*256 + c)*HW + j]
    // out element : sampled[((c*900 + q)*6 + n)*4 + l]
    const int    c0i = chbase + c8;
    const float* pA  = fA + (size_t)(n * NCH + c0i) * (size_t)HWA;
    const float* pB  = fB + (size_t)(n * NCH + c0i) * (size_t)HWB;
    float*       op  = sampled + ((size_t)c0i * NQ + q) * (NCAM * 4) + n * 4;
    const bool   dostore = ((lane & 3) == 0);   // xside==0 && lp==0

    #pragma unroll
    for (int ci = 0; ci < 8; ci++) {
        // pair lanes' j differ by 1 -> same 128B line, one wavefront per row-load
        float a = fmaf(wA0, __ldg(pA + (ci * 8) * HWA + jA0),
                       wA1 * __ldg(pA + (ci * 8) * HWA + jA1));   // level 2*lp
        float b = fmaf(wB0, __ldg(pB + (ci * 8) * HWB + jB0),
                       wB1 * __ldg(pB + (ci * 8) * HWB + jB1));   // level 2*lp+1
        // complete bilinear sums across the (xc0, xc1) lane pair
        a += __shfl_xor_sync(0xffffffffu, a, 1);
        b += __shfl_xor_sync(0xffffffffu, b, 1);
        // exchange level pairs: lp=0 lane gets lp=1 lane's (levels 2,3)
        const float a2 = __shfl_xor_sync(0xffffffffu, a, 2);
        const float b2 = __shfl_xor_sync(0xffffffffu, b, 2);
        if (dostore) {
            // one 16B store covers all 4 levels of this (c,q,n)
            *reinterpret_cast<float4*>(op + (size_t)(ci * 8) * (NQ * NCAM * 4)) =
                make_float4(a, b, a2, b2);
        }
    }
}

extern "C" void kernel_launch(void* const* d_in, const int* in_sizes, int n_in,
                              void* d_out, int out_size) {
    const float* f0  = (const float*)d_in[0];
    const float* f1  = (const float*)d_in[1];
    const float* f2  = (const float*)d_in[2];
    const float* f3  = (const float*)d_in[3];
    const float* ref = (const float*)d_in[4];
    const float* pc  = (const float*)d_in[5];
    const float* img = (const float*)d_in[6];
    const float* l2i = (const float*)d_in[7];
    float* out = (float*)d_out;

    // 1) zero-fill sampled + copy ref3d: 5400*256 threads, one float4 each
    fs_fill<<<NSAMP, 256>>>(ref, out);
    // 2) gather valid samples (writes mask for all samples, overwrites valid
    //    sampled positions): 2700 blocks x 8 warps = 4 warps per sample
    fs_gather<<<NSAMP / 2, 256>>>(f0, f1, f2, f3, ref, pc, img, l2i, out);
}

// round 16
// speedup vs baseline: 1.9391x; 1.9391x over previous
#include <cuda_runtime.h>
#include <cuda_bf16.h>

// DETR3D feature sampling. B=1, NC=6 cams, C=256, nq=900, 4 FPN levels
// (H,W): (116,200) (58,100) (29,50) (15,25).
// Output: ref3d[900,3] | sampled[256,900,6,1,4] | mask[900,6].
//
// Structure = the measured 21.0us winner (R12): block = 192 threads =
// 8 queries x 6 cams x (2 level-halves x 2 xsides); lanes (t, t^1) share one
// sample and pair-coalesce the two x columns of the bilinear quad into one
// L1 wavefront per row-load; bilinear sum completes with one __shfl_xor(+).
// Two level passes (l = lhalf + 2*lv), scalar stores, CPB=16 -> 1808 blocks.
// (R13 merged-level float2 stores and R14 fill+gather split both REGRESSED:
// long shfl dependency chains / work concentration kill latency hiding.)
//
// R15 delta: warp-uniform dead-pass skip. Within one lv pass a warp's 16
// (sample,level) lanes cover 8 distinct samples; with ~87% of samples
// out-of-frustum, ~33% of warp-passes have NO valid lane. Those passes now
// take a store-only branch (16 coalesced zero STGs) and skip all LDG + SHFL
// LSU dispatch, which the R12 profile (L1=66%, DRAM=1.8%, all-L2-resident)
// says is a major cost. Branch is warp-uniform (ballot) -> no divergence;
// shfl only executes in the fully-active branch.

#define FS_EPS 1e-5f
#define NQ 900
#define NCAM 6
#define NCH 256
#define QPB 8              // queries per block
#define CPB 16             // channels per chunk (grid.y)
#define THREADS (QPB * NCAM * 4)   // 192

__global__ __launch_bounds__(THREADS, 8)
void fs_sample_kernel(
    const float* __restrict__ f0,   // [6,256,116,200]
    const float* __restrict__ f1,   // [6,256, 58,100]
    const float* __restrict__ f2,   // [6,256, 29, 50]
    const float* __restrict__ f3,   // [6,256, 15, 25]
    const float* __restrict__ ref,  // [900,3]
    const float* __restrict__ pc,   // [6]
    const float* __restrict__ img,  // [2] = {H=928, W=1600}
    const float* __restrict__ l2i,  // [6,4,4]
    float* __restrict__ out)
{
    const int t     = threadIdx.x;       // 0..191
    const int xside = t & 1;             // which x column of the bilinear pair
    const int lhalf = (t >> 1) & 1;      // levels {lhalf, lhalf+2}
    const int s     = t >> 2;            // 0..47 = qsub*6 + n
    const int qsub  = s / NCAM;
    const int n     = s - qsub * NCAM;
    const int q     = blockIdx.x * QPB + qsub;
    const int cbase = blockIdx.y * CPB;

    float* sampled = out + NQ * 3;                       // 2700
    float* maskout = out + NQ * 3 + NCH * NQ * NCAM * 4; // 2700 + 5529600

    // ref3d passthrough (channel-chunk 0 blocks only)
    if (blockIdx.y == 0 && t < QPB * 3) {
        int qq = blockIdx.x * QPB + t / 3;
        if (qq < NQ) out[qq * 3 + (t % 3)] = ref[qq * 3 + (t % 3)];
    }

    const bool active = (q < NQ);

    // --- projection (level-independent, matches reference arithmetic) ---
    float gx = 0.f, gy = 0.f;
    if (active) {
        const float rx = ref[q * 3 + 0];
        const float ry = ref[q * 3 + 1];
        const float rz = ref[q * 3 + 2];
        const float px = rx * (pc[3] - pc[0]) + pc[0];
        const float py = ry * (pc[4] - pc[1]) + pc[1];
        const float pz = rz * (pc[5] - pc[2]) + pc[2];
        const float* M = l2i + n * 16;
        const float c0 = M[0] * px + M[1] * py + M[2]  * pz + M[3];
        const float c1 = M[4] * px + M[5] * py + M[6]  * pz + M[7];
        const float c2 = M[8] * px + M[9] * py + M[10] * pz + M[11];
        const float zd = fmaxf(c2, FS_EPS);
        gx = (c0 / zd / img[1] - 0.5f) * 2.0f;
        gy = (c1 / zd / img[0] - 0.5f) * 2.0f;

        if ((t & 3) == 0 && blockIdx.y == 0) {
            const bool m = (c2 > FS_EPS) &&
                           (gx > -1.0f) && (gx < 1.0f) &&
                           (gy > -1.0f) && (gy < 1.0f);
            maskout[q * NCAM + n] = m ? 1.0f : 0.0f;
        }
    }

    #pragma unroll
    for (int lv = 0; lv < 2; lv++) {
        const int l = lhalf + 2 * lv;        // this thread's level

        const int   Wl = (l == 0) ? 200 : (l == 1) ? 100 : (l == 2) ? 50 : 25;
        const int   Hl = (l == 0) ? 116 : (l == 1) ?  58 : (l == 2) ? 29 : 15;
        const int   HW = Wl * Hl;
        const float* featb = (l == 0) ? f0 : (l == 1) ? f1 : (l == 2) ? f2 : f3;

        int   j0 = 0, j1 = 0;
        float w0 = 0.f, w1 = 0.f;
        bool  doload = false;

        if (active) {
            const float ix  = ((gx + 1.0f) * (float)Wl - 1.0f) * 0.5f;
            const float iy  = ((gy + 1.0f) * (float)Hl - 1.0f) * 0.5f;
            const float ix0 = floorf(ix);
            const float iy0 = floorf(iy);
            const float wx1 = ix - ix0;
            const float wy1 = iy - iy0;
            const float wx0 = 1.0f - wx1;
            const float wy0 = 1.0f - wy1;

            // side validity (NaN comparisons are false -> anyvalid false)
            const bool vx0 = (ix0        >= 0.0f) && (ix0        <= (float)(Wl - 1));
            const bool vx1 = (ix0 + 1.0f >= 0.0f) && (ix0 + 1.0f <= (float)(Wl - 1));
            const bool vy0 = (iy0        >= 0.0f) && (iy0        <= (float)(Hl - 1));
            const bool vy1 = (iy0 + 1.0f >= 0.0f) && (iy0 + 1.0f <= (float)(Hl - 1));
            const bool anyvalid = (vx0 | vx1) & (vy0 | vy1);  // identical for both pair lanes

            if (anyvalid) {
                // anyvalid implies ix0 in [-1, Wl-1], iy0 in [-1, Hl-1] -> safe int conv
                const int ixi = (int)ix0;
                const int iyi = (int)iy0;
                const int xc0 = max(ixi,     0);
                const int xc1 = min(ixi + 1, Wl - 1);
                const int yr0 = max(iyi,     0) * Wl;
                const int yr1 = min(iyi + 1, Hl - 1) * Wl;

                const int   xs  = xside ? xc1 : xc0;   // this lane's column (clamped)
                const bool  vxs = xside ? vx1 : vx0;
                const float wxs = xside ? wx1 : wx0;
                j0 = yr0 + xs;
                j1 = yr1 + xs;
                w0 = (vy0 && vxs) ? wy0 * wxs : 0.f;   // zero invalid corners (exact)
                w1 = (vy1 && vxs) ? wy1 * wxs : 0.f;
                doload = true;                          // uniform across the pair
            }
        }

        // --- channel loop ---
        // feat element: featb[(n*256 + c)*HW + j]
        // out element : sampled[((c*900 + q)*6 + n)*4 + l]
        const float* p  = featb + (size_t)(n * NCH + cbase) * (size_t)HW;
        float*       op = sampled + ((size_t)cbase * NQ + q) * (NCAM * 4) + n * 4 + l;
        const bool   dostore = active && (xside == 0);

        // R15: warp-uniform dead-pass skip (~33% of warp-passes have no
        // valid lane -> store-only loop, no LDG/SHFL dispatch at all)
        const unsigned bal = __ballot_sync(0xffffffffu, doload);
        if (bal == 0u) {
            #pragma unroll
            for (int cc = 0; cc < CPB; cc++) {
                if (dostore) op[(size_t)cc * (NQ * NCAM * 4)] = 0.0f;
            }
        } else {
            #pragma unroll
            for (int cc = 0; cc < CPB; cc++) {
                float acc = 0.0f;
                if (doload) {
                    // pair lanes' j differ by 1 -> same line, one wavefront per LDG
                    acc = fmaf(w0, __ldg(p + cc * HW + j0),
                               w1 * __ldg(p + cc * HW + j1));
                }
                // complete bilinear sum across the (xc0, xc1) lane pair
                const float sum = acc + __shfl_xor_sync(0xffffffffu, acc, 1);
                if (dostore) op[(size_t)cc * (NQ * NCAM * 4)] = sum;
            }
        }
    }
}

extern "C" void kernel_launch(void* const* d_in, const int* in_sizes, int n_in,
                              void* d_out, int out_size) {
    const float* f0  = (const float*)d_in[0];
    const float* f1  = (const float*)d_in[1];
    const float* f2  = (const float*)d_in[2];
    const float* f3  = (const float*)d_in[3];
    const float* ref = (const float*)d_in[4];
    const float* pc  = (const float*)d_in[5];
    const float* img = (const float*)d_in[6];
    const float* l2i = (const float*)d_in[7];
    float* out = (float*)d_out;

    dim3 grid((NQ + QPB - 1) / QPB, NCH / CPB);  // (113, 16) = 1808 blocks
    fs_sample_kernel<<<grid, THREADS>>>(f0, f1, f2, f3, ref, pc, img, l2i, out);
}